// round 10
// baseline (speedup 1.0000x reference)
#include <cuda_runtime.h>
#include <cuda_fp16.h>

// cumulative_hazard R9: tensor-core RNN, k8 formulation.
// RNN step: C_init = splat(y_row) * w8 + bias  (2 HFMA2 with lane-select splats,
// off the critical chain), then mma.m16n8k8 with d != c, tanh.approx.f16x2 on D,
// which IS the next A fragment. Step 0 has flow==0 -> f = tanh(C_init), no mma.
// f2 layers 0/1 = mma.m16n8k8 d!=c. Output layer = f32 dot + quad shfl reduce.

typedef unsigned u32;

#define NTHREADS 256
#define ROWS_PER_BLOCK 512   // 8 warps x 64 rows

__device__ __forceinline__ __half2 u2h(u32 v) { return *reinterpret_cast<__half2*>(&v); }
__device__ __forceinline__ u32 h2u2(__half2 v) { return *reinterpret_cast<u32*>(&v); }
__device__ __forceinline__ u32 h2u(__half lo, __half hi) {
    __half2 v = __halves2half2(lo, hi);
    return *reinterpret_cast<u32*>(&v);
}
__device__ __forceinline__ u32 tanh_u(u32 v) {
    asm("tanh.approx.f16x2 %0, %0;" : "+r"(v));
    return v;
}
// mma m16n8k8 f16, separate D and C (no accumulator copy needed)
__device__ __forceinline__ void mma1688_dc(u32& d0, u32& d1,
                                           u32 a0, u32 a1, u32 b0,
                                           u32 c0, u32 c1) {
    asm("mma.sync.aligned.m16n8k8.row.col.f16.f16.f16.f16 "
        "{%0,%1}, {%2,%3}, {%4}, {%5,%6};"
        : "=r"(d0), "=r"(d1)
        : "r"(a0), "r"(a1), "r"(b0), "r"(c0), "r"(c1));
}

__device__ __forceinline__ float softplus_out(float x) {
    float ax = fabsf(x);
    float l = log1pf(__expf(-ax));
    return x > 0.0f ? x + l : l;
}
__device__ __forceinline__ float sp_precise(float x) {
    float ax = fabsf(x);
    float l = log1pf(expf(-ax));
    return x > 0.0f ? x + l : l;
}

__global__ __launch_bounds__(NTHREADS)
void hazard_kernel(const float* __restrict__ Y,     // [N,16]
                   const float* __restrict__ tau,   // [N,1]
                   const float* __restrict__ f1W,   // [8,9]
                   const float* __restrict__ f1b,   // [8]
                   const float* __restrict__ ftW,   // [8,1]
                   const float* __restrict__ ftb,   // [8]
                   const float* __restrict__ f20W,  // [8,8]
                   const float* __restrict__ f20b,  // [8]
                   const float* __restrict__ f21W,  // [8,8]
                   const float* __restrict__ f21b,  // [8]
                   const float* __restrict__ f22W,  // [1,8]
                   const float* __restrict__ f22b,  // [1]
                   float* __restrict__ out,         // [N]
                   int N)
{
    __shared__ __half sW1[72], sB1[8];
    __shared__ __half sW20[64], sB20[8], sTW[8];
    __shared__ __half sW21[64], sB21[8];
    __shared__ float  sW22f[8];
    __shared__ float  sB22f;
    // y: [warp][tile][g][j] as half2(row g, row g+8);  tau: [warp][tile][g]
    __shared__ u32 sY[8 * 4 * 8 * 11];
    __shared__ u32 sTau[8 * 4 * 8];

    const int t = threadIdx.x;
    // ---- weight preprocessing (softplus folded; f16) ----
    if (t < 72)        { sW1[t] = __float2half(f1W[t]); }
    else if (t < 80)   { int i = t - 72;  sB1[i]  = __float2half(f1b[i]); }
    else if (t < 144)  { int i = t - 80;  sW20[i] = __float2half(f20W[i]); }
    else if (t < 152)  { int i = t - 144; sB20[i] = __float2half(f20b[i] + sp_precise(ftb[i])); }
    else if (t < 160)  { int i = t - 152; sTW[i]  = __float2half(sp_precise(ftW[i])); }
    else if (t < 224)  { int i = t - 160; sW21[i] = __float2half(sp_precise(f21W[i])); }
    else if (t < 232)  { int i = t - 224; sB21[i] = __float2half(sp_precise(f21b[i])); }
    else if (t < 240)  { int i = t - 232; sW22f[i] = sp_precise(f22W[i]); }
    else if (t == 240) { sB22f = sp_precise(f22b[0]); }
    __syncthreads();

    const int lane = t & 31;
    const int warp = t >> 5;
    const int g  = lane >> 2;   // 0..7  (fragment row within half-tile / col n)
    const int tq = lane & 3;    // 0..3  (fragment col group / k group)

    const long long base = (long long)blockIdx.x * ROWS_PER_BLOCK;

    // ---- load 2 rows, compute log-gaps, stage y & tau into shared ----
    {
        const int rp = 2 * t;                       // local rows rp, rp+1
        long long r0 = base + rp;
        if (r0 > (long long)N - 2) r0 = (long long)N - 2;   // clamp (dup rows, stores predicated)

        const float4* yp = (const float4*)(Y + r0 * 16);
        float4 q0 = yp[0], q1 = yp[1], q2 = yp[2], q3 = yp[3];
        float4 p0 = yp[4], p1 = yp[5], p2 = yp[6], p3 = yp[7];
        float ra[16] = { q0.x,q0.y,q0.z,q0.w, q1.x,q1.y,q1.z,q1.w,
                         q2.x,q2.y,q2.z,q2.w, q3.x,q3.y,q3.z,q3.w };
        float rb[16] = { p0.x,p0.y,p0.z,p0.w, p1.x,p1.y,p1.z,p1.w,
                         p2.x,p2.y,p2.z,p2.w, p3.x,p3.y,p3.z,p3.w };

        __half* yh = reinterpret_cast<__half*>(sY);
        __half* th = reinterpret_cast<__half*>(sTau);

        // both rows rp, rp+1 share (warp, tile, half); g = even/odd pair
        const int tile = (rp >> 4) & 3;
        const int hs   = (rp >> 3) & 1;
        const int g0   = rp & 7;          // even
#pragma unroll
        for (int j = 0; j < 11; j++) {
            float d0 = __logf(ra[4 + j] - ra[3 + j] + 0.1f);
            float d1 = __logf(rb[4 + j] - rb[3 + j] + 0.1f);
            int i0 = (((warp * 4 + tile) * 8 + g0)     * 11 + j) * 2 + hs;
            int i1 = (((warp * 4 + tile) * 8 + g0 + 1) * 11 + j) * 2 + hs;
            yh[i0] = __float2half(d0);
            yh[i1] = __float2half(d1);
        }
        float2 tv = *(const float2*)(tau + r0);
        th[((warp * 4 + tile) * 8 + g0)     * 2 + hs] = __float2half(tv.x);
        th[((warp * 4 + tile) * 8 + g0 + 1) * 2 + hs] = __float2half(tv.y);
    }
    __syncwarp();   // writer warp == owner warp for all staged data

    // ---- per-thread fragment weights ----
    const u32 w1b0   = h2u(sW1[g * 9 + 2 * tq], sW1[g * 9 + 2 * tq + 1]);   // B: W1[n=g][k=2tq..]
    const __half2 w8p = __halves2half2(sW1[(2 * tq) * 9 + 8],               // y-col weights for n=2tq,2tq+1
                                       sW1[(2 * tq + 1) * 9 + 8]);
    const __half2 bc1 = __halves2half2(sB1[2 * tq], sB1[2 * tq + 1]);
    const u32 w20b  = h2u(sW20[g * 8 + 2 * tq], sW20[g * 8 + 2 * tq + 1]);
    const __half2 b20p = __halves2half2(sB20[2 * tq], sB20[2 * tq + 1]);
    const __half2 tWp  = __halves2half2(sTW[2 * tq], sTW[2 * tq + 1]);
    const u32 w21b  = h2u(sW21[g * 8 + 2 * tq], sW21[g * 8 + 2 * tq + 1]);
    const u32 b21p  = h2u(sB21[2 * tq], sB21[2 * tq + 1]);
    const float w22a = sW22f[2 * tq], w22c = sW22f[2 * tq + 1];
    const float b22  = sB22f;

    const u32* yW  = sY + (warp * 4) * 8 * 11;   // this warp's y block
    const u32* tW2 = sTau + (warp * 4) * 8;

    // ---- RNN: 4 fragments (64 rows), 11 steps ----
    u32 f0[4], f1r[4];   // C/A fragment: reg0 rows g, reg1 rows g+8; cols 2tq,2tq+1

    // step 0: flow == 0  ->  f = tanh(C_init) with C_init = splat(y)*w8 + b
#pragma unroll
    for (int tile = 0; tile < 4; tile++) {
        __half2 yh2 = u2h(yW[(tile * 8 + g) * 11]);
        f0[tile]  = tanh_u(h2u2(__hfma2(__low2half2(yh2),  w8p, bc1)));
        f1r[tile] = tanh_u(h2u2(__hfma2(__high2half2(yh2), w8p, bc1)));
    }

#pragma unroll
    for (int j = 1; j < 11; j++) {
#pragma unroll
        for (int tile = 0; tile < 4; tile++) {
            __half2 yh2 = u2h(yW[(tile * 8 + g) * 11 + j]);   // (y row g, y row g+8)
            u32 c0 = h2u2(__hfma2(__low2half2(yh2),  w8p, bc1));  // off-chain C init
            u32 c1 = h2u2(__hfma2(__high2half2(yh2), w8p, bc1));
            u32 d0, d1;
            mma1688_dc(d0, d1, f0[tile], f1r[tile], w1b0, c0, c1);
            f0[tile]  = tanh_u(d0);
            f1r[tile] = tanh_u(d1);
        }
    }

    // ---- f2 layer 0: tanh(flow @ W20^T + b20' + tau*sp(Wtau)) ----
#pragma unroll
    for (int tile = 0; tile < 4; tile++) {
        __half2 tp = u2h(tW2[tile * 8 + g]);
        u32 c0 = h2u2(__hfma2(__low2half2(tp),  tWp, b20p));
        u32 c1 = h2u2(__hfma2(__high2half2(tp), tWp, b20p));
        u32 d0, d1;
        mma1688_dc(d0, d1, f0[tile], f1r[tile], w20b, c0, c1);
        f0[tile]  = tanh_u(d0);
        f1r[tile] = tanh_u(d1);
    }

    // ---- f2 layer 1: tanh(g @ sp(W21)^T + sp(b21)) ----
#pragma unroll
    for (int tile = 0; tile < 4; tile++) {
        u32 d0, d1;
        mma1688_dc(d0, d1, f0[tile], f1r[tile], w21b, b21p, b21p);
        f0[tile]  = tanh_u(d0);
        f1r[tile] = tanh_u(d1);
    }

    // ---- output layer: f32 dot over 8 cols (quad-distributed) + shfl reduce ----
#pragma unroll
    for (int tile = 0; tile < 4; tile++) {
        float2 fa = __half22float2(u2h(f0[tile]));   // row g:   cols 2tq,2tq+1
        float2 fb = __half22float2(u2h(f1r[tile]));  // row g+8
        float pl = fa.x * w22a + fa.y * w22c;
        float ph = fb.x * w22a + fb.y * w22c;
        pl += __shfl_xor_sync(0xFFFFFFFFu, pl, 1);
        pl += __shfl_xor_sync(0xFFFFFFFFu, pl, 2);
        ph += __shfl_xor_sync(0xFFFFFFFFu, ph, 1);
        ph += __shfl_xor_sync(0xFFFFFFFFu, ph, 2);
        if (tq == 0) {
            long long rlo = base + warp * 64 + tile * 16 + g;
            long long rhi = rlo + 8;
            if (rlo < N) out[rlo] = softplus_out(pl + b22);
            if (rhi < N) out[rhi] = softplus_out(ph + b22);
        }
    }
}

extern "C" void kernel_launch(void* const* d_in, const int* in_sizes, int n_in,
                              void* d_out, int out_size)
{
    const float* Y    = (const float*)d_in[0];
    const float* tau  = (const float*)d_in[1];
    const float* f1W  = (const float*)d_in[2];
    const float* f1b  = (const float*)d_in[3];
    const float* ftW  = (const float*)d_in[4];
    const float* ftb  = (const float*)d_in[5];
    const float* f20W = (const float*)d_in[6];
    const float* f20b = (const float*)d_in[7];
    const float* f21W = (const float*)d_in[8];
    const float* f21b = (const float*)d_in[9];
    const float* f22W = (const float*)d_in[10];
    const float* f22b = (const float*)d_in[11];
    float* out = (float*)d_out;

    int N = out_size;
    int blocks = (N + ROWS_PER_BLOCK - 1) / ROWS_PER_BLOCK;
    hazard_kernel<<<blocks, NTHREADS>>>(Y, tau, f1W, f1b, ftW, ftb,
                                        f20W, f20b, f21W, f21b, f22W, f22b,
                                        out, N);
}